// round 3
// baseline (speedup 1.0000x reference)
#include <cuda_runtime.h>

#define VSIZE 100000
#define EDIM  128
#define DA    60
#define BN    4096
#define TN    8
#define CN    200
#define EPSV  1e-6f
#define CCH   100

typedef unsigned long long ull;

// Scratch (device globals: no allocation allowed)
__device__ float g_cprojn[(size_t)VSIZE * DA];   // normalized c projections [V,60]
__device__ float g_tprojn[(size_t)BN * TN * DA]; // normalized t projections [B*T,60]
__device__ float g_Mt[EDIM * EDIM];              // Mt[k][e] = (R_w @ Bc_w)[e][k]
__device__ float g_bias2[EDIM];                  // R_w @ Bc_b + R_b

// ---------------------------------------------------------------------------
// packed fp32x2 helpers (Blackwell FFMA2 path — ptxas never emits it from C++)
// ---------------------------------------------------------------------------
__device__ __forceinline__ ull ffma2(ull a, ull b, ull c) {
    ull d; asm("fma.rn.f32x2 %0,%1,%2,%3;" : "=l"(d) : "l"(a), "l"(b), "l"(c));
    return d;
}
__device__ __forceinline__ ull dup2(float x) {
    ull r; asm("mov.b64 %0,{%1,%1};" : "=l"(r) : "f"(x)); return r;
}
__device__ __forceinline__ float2 upk(ull v) {
    float a, b; asm("mov.b64 {%0,%1},%2;" : "=f"(a), "=f"(b) : "l"(v));
    return make_float2(a, b);
}

// ---------------------------------------------------------------------------
// Kernel 0: fuse M = R_w @ Bc_w (stored transposed) and bias2 = R_w@Bc_b + R_b
// ---------------------------------------------------------------------------
__global__ void fuse_kernel(const float* __restrict__ Rw, const float* __restrict__ Bw,
                            const float* __restrict__ Bb, const float* __restrict__ Rb)
{
    int e = blockIdx.x;
    int k = threadIdx.x;
    __shared__ float sR[EDIM];
    __shared__ float sP[EDIM];
    sR[k] = Rw[e * EDIM + k];
    __syncthreads();
    float acc = 0.f;
#pragma unroll 8
    for (int j = 0; j < EDIM; j++)
        acc = fmaf(sR[j], Bw[j * EDIM + k], acc);
    g_Mt[k * EDIM + e] = acc;     // transposed store
    sP[k] = sR[k] * Bb[k];
    __syncthreads();
    if (k == 0) {
        float s = 0.f;
        for (int j = 0; j < EDIM; j++) s += sP[j];
        g_bias2[e] = s + Rb[e];
    }
}

// ---------------------------------------------------------------------------
// Kernel 1/2: project rows through W[DA,E] + bias, normalize (eps-clamped L2).
// 16 rows per 256-thread block, FFMA2 inner loop.
// ---------------------------------------------------------------------------
template <bool GATHER>
__global__ __launch_bounds__(256)
void proj_kernel(const float* __restrict__ table,
                 const float* __restrict__ W,
                 const float* __restrict__ bias,
                 const int* __restrict__ idx)
{
    __shared__ __align__(16) float sW[DA][132];
    __shared__ __align__(16) float sRow[16][132];
    __shared__ float sOut[16][64];
    __shared__ float sB[64];

    float* out = GATHER ? g_tprojn : g_cprojn;
    int tid = threadIdx.x;
    int w = tid >> 5, l = tid & 31;

    for (int i = tid; i < DA * EDIM; i += 256)
        sW[i >> 7][i & 127] = W[i];
    if (tid < 64) sB[tid] = (tid < DA) ? bias[tid] : 0.f;

#pragma unroll
    for (int h = 0; h < 2; h++) {
        int r = w + 8 * h;
        int gr = blockIdx.x * 16 + r;
        int rowv = GATHER ? idx[gr] : gr;
        float4 x = ((const float4*)(table + (size_t)rowv * EDIM))[l];
        ((float4*)&sRow[r][0])[l] = x;
    }
    __syncthreads();

    {
        int rb = l >> 2, dq = l & 3;
        int d0 = w * 8 + dq, d1 = d0 + 4;
        bool ok1 = d1 < DA;
        const ulonglong2* w0r = (const ulonglong2*)&sW[d0][0];
        const ulonglong2* w1r = (const ulonglong2*)&sW[ok1 ? d1 : 0][0];
#pragma unroll
        for (int h = 0; h < 2; h++) {
            int r = 8 * h + rb;
            const ulonglong2* xr = (const ulonglong2*)&sRow[r][0];
            ull a0 = 0, b0 = 0, a1 = 0, b1 = 0;
#pragma unroll
            for (int q = 0; q < 32; q++) {
                ulonglong2 xv = xr[q];
                ulonglong2 wa = w0r[q];
                a0 = ffma2(xv.x, wa.x, a0);
                b0 = ffma2(xv.y, wa.y, b0);
                ulonglong2 wb = w1r[q];
                a1 = ffma2(xv.x, wb.x, a1);
                b1 = ffma2(xv.y, wb.y, b1);
            }
            float2 fa = upk(a0), fb = upk(b0);
            sOut[r][d0] = fa.x + fa.y + fb.x + fb.y + sB[d0];
            if (ok1) {
                float2 fc = upk(a1), fd = upk(b1);
                sOut[r][d1] = fc.x + fc.y + fd.x + fd.y + sB[d1];
            }
        }
    }
    __syncthreads();

#pragma unroll
    for (int h = 0; h < 2; h++) {
        int r = w + 8 * h;
        float v0 = sOut[r][l];
        float v1 = (l + 32 < DA) ? sOut[r][l + 32] : 0.f;
        float ss = v0 * v0 + v1 * v1;
#pragma unroll
        for (int o = 16; o >= 1; o >>= 1)
            ss += __shfl_xor_sync(0xffffffffu, ss, o);
        float inv = 1.0f / fmaxf(sqrtf(ss), EPSV);
        int gr = blockIdx.x * 16 + r;
        float* op = out + (size_t)gr * DA;
        op[l] = v0 * inv;
        if (l + 32 < DA) op[l + 32] = v1 * inv;
    }
}

// ---------------------------------------------------------------------------
// Kernel 3: main. One CTA per batch row b. 256 threads (8 warps).
//  P1: stage cprojn chunk in smem; warp w computes all scores for t=w,
//      lanes own c-columns -> softmax fully in registers (no shuffles for dot)
//  P3: warp w owns e-slice [16w,16w+16); lane=(t=l>>2, eq=l&3) walks ALL c.
//      No partial sums, no reductions. s written directly to s_p[k][t].
//  P4: same slice layout over Mt; output written directly, bias fused.
// ---------------------------------------------------------------------------
__global__ __launch_bounds__(256)
void main_kernel(const float* __restrict__ cvec,
                 const int* __restrict__ citems,
                 const int* __restrict__ maskp,
                 float* __restrict__ outp)
{
    __shared__ int   s_cit[CN];
    __shared__ int   s_mask[CN];
    __shared__ __align__(16) float s_tp[TN][64];
    __shared__ __align__(16) float s_cp[CCH][68];   // pad 68 -> conflict-free float4
    __shared__ __align__(16) float s_aT[CN][8];     // attn [c][t]
    __shared__ __align__(16) float s_p[EDIM][8];    // s transposed [k][t]

    int b = blockIdx.x;
    int tid = threadIdx.x;
    int w = tid >> 5, l = tid & 31;

    if (tid < CN) {
        s_cit[tid]  = citems[b * CN + tid];
        s_mask[tid] = maskp[b * CN + tid];
    }
    for (int i = tid; i < TN * DA; i += 256) {
        int t = i / DA, d = i - t * DA;
        s_tp[t][d] = g_tprojn[(size_t)b * (TN * DA) + i];
    }

    // ---- Phase 1: scores. lane l owns c = ch*100 + l + 32k ----
    float sc[8];
#pragma unroll
    for (int i = 0; i < 8; i++) sc[i] = -1e30f;

    for (int ch = 0; ch < 2; ch++) {
        __syncthreads();                       // protect s_cp reuse (+init on ch=0)
        int base = ch * CCH;
        for (int r = w; r < CCH; r += 8) {
            int tok = s_cit[base + r];
            if (l < 30) {
                float2 v = ((const float2*)(g_cprojn + (size_t)tok * DA))[l];
                *(float2*)&s_cp[r][2 * l] = v;
            }
        }
        __syncthreads();

        ull a0 = 0, a1 = 0, a2 = 0, a3 = 0;
#pragma unroll
        for (int d4 = 0; d4 < 15; d4++) {
            ulonglong2 tp = *(const ulonglong2*)&s_tp[w][4 * d4];
            ulonglong2 c0 = *(const ulonglong2*)&s_cp[l][4 * d4];
            a0 = ffma2(c0.x, tp.x, a0); a0 = ffma2(c0.y, tp.y, a0);
            ulonglong2 c1 = *(const ulonglong2*)&s_cp[l + 32][4 * d4];
            a1 = ffma2(c1.x, tp.x, a1); a1 = ffma2(c1.y, tp.y, a1);
            ulonglong2 c2 = *(const ulonglong2*)&s_cp[l + 64][4 * d4];
            a2 = ffma2(c2.x, tp.x, a2); a2 = ffma2(c2.y, tp.y, a2);
            if (l < 4) {
                ulonglong2 c3 = *(const ulonglong2*)&s_cp[l + 96][4 * d4];
                a3 = ffma2(c3.x, tp.x, a3); a3 = ffma2(c3.y, tp.y, a3);
            }
        }
        {
            float2 f;
            f = upk(a0); sc[ch*4+0] = s_mask[base + l]      ? -1e30f : (f.x + f.y);
            f = upk(a1); sc[ch*4+1] = s_mask[base + l + 32] ? -1e30f : (f.x + f.y);
            f = upk(a2); sc[ch*4+2] = s_mask[base + l + 64] ? -1e30f : (f.x + f.y);
            if (l < 4) {
                f = upk(a3); sc[ch*4+3] = s_mask[base + l + 96] ? -1e30f : (f.x + f.y);
            }
        }
    }

    // ---- Phase 2: softmax over c for t=w (registers + butterflies only) ----
    {
        float m = sc[0];
#pragma unroll
        for (int i = 1; i < 8; i++) m = fmaxf(m, sc[i]);
#pragma unroll
        for (int o = 16; o >= 1; o >>= 1)
            m = fmaxf(m, __shfl_xor_sync(0xffffffffu, m, o));
        float sum = 0.f;
#pragma unroll
        for (int i = 0; i < 8; i++) { sc[i] = __expf(sc[i] - m); sum += sc[i]; }
#pragma unroll
        for (int o = 16; o >= 1; o >>= 1)
            sum += __shfl_xor_sync(0xffffffffu, sum, o);
        float inv = 1.0f / sum;
#pragma unroll
        for (int i = 0; i < 8; i++) {
            int cl = l + 32 * (i & 3);
            if (cl < CCH) s_aT[(i >> 2) * CCH + cl][w] = sc[i] * inv;
        }
    }
    __syncthreads();

    // ---- Phase 3: s = attn @ u over full c; warp owns e-slice ----
    int t = l >> 2, eq = l & 3;
    int ebase = 16 * w + 4 * eq;
    {
        ull p0 = 0, p1 = 0;
        int tok = s_cit[0];
#pragma unroll 4
        for (int c = 0; c < CN; c++) {
            const ulonglong2* up = (const ulonglong2*)(cvec + (size_t)tok * EDIM + ebase);
            if (c + 1 < CN) tok = s_cit[c + 1];     // pipeline next token id
            ulonglong2 u = *up;
            ull ad = dup2(s_aT[c][t]);
            p0 = ffma2(u.x, ad, p0);
            p1 = ffma2(u.y, ad, p1);
        }
        float2 f0 = upk(p0), f1 = upk(p1);
        s_p[ebase + 0][t] = f0.x;
        s_p[ebase + 1][t] = f0.y;
        s_p[ebase + 2][t] = f1.x;
        s_p[ebase + 3][t] = f1.y;
    }
    __syncthreads();

    // ---- Phase 4: z = s @ Mt + bias2, direct output ----
    {
        ull z0 = 0, z1 = 0;
#pragma unroll 4
        for (int k = 0; k < EDIM; k++) {
            ulonglong2 mt = *(const ulonglong2*)(g_Mt + k * EDIM + ebase);
            ull sv = dup2(s_p[k][t]);
            z0 = ffma2(mt.x, sv, z0);
            z1 = ffma2(mt.y, sv, z1);
        }
        float4 bb = *(const float4*)(g_bias2 + ebase);
        float2 f0 = upk(z0), f1 = upk(z1);
        float4 res = make_float4(f0.x + bb.x, f0.y + bb.y, f1.x + bb.z, f1.y + bb.w);
        *(float4*)(outp + (size_t)b * (TN * EDIM) + t * EDIM + ebase) = res;
    }
}

// ---------------------------------------------------------------------------
extern "C" void kernel_launch(void* const* d_in, const int* in_sizes, int n_in,
                              void* d_out, int out_size)
{
    const float* tvec  = (const float*)d_in[0];
    const float* cvec  = (const float*)d_in[1];
    const float* Ac_w  = (const float*)d_in[2];
    const float* Ac_b  = (const float*)d_in[3];
    const float* At_w  = (const float*)d_in[4];
    const float* At_b  = (const float*)d_in[5];
    const float* Bc_w  = (const float*)d_in[6];
    const float* Bc_b  = (const float*)d_in[7];
    const float* R_w   = (const float*)d_in[8];
    const float* R_b   = (const float*)d_in[9];
    const int*   titems = (const int*)d_in[10];
    const int*   citems = (const int*)d_in[11];
    const int*   maskp  = (const int*)d_in[12];

    fuse_kernel<<<EDIM, EDIM>>>(R_w, Bc_w, Bc_b, R_b);
    proj_kernel<false><<<VSIZE / 16, 256>>>(cvec, Ac_w, Ac_b, nullptr);
    proj_kernel<true><<<(BN * TN) / 16, 256>>>(tvec, At_w, At_b, titems);
    main_kernel<<<BN, 256>>>(cvec, citems, maskp, (float*)d_out);
}

// round 4
// speedup vs baseline: 1.5558x; 1.5558x over previous
#include <cuda_runtime.h>

#define VSIZE 100000
#define EDIM  128
#define DA    60
#define BN    4096
#define TN    8
#define CN    200
#define EPSV  1e-6f
#define CCH   100

typedef unsigned long long ull;

// Scratch (device globals: no allocation allowed)
__device__ float g_cprojn[(size_t)VSIZE * DA];     // normalized c projections [V,60]
__device__ float g_tprojn[(size_t)BN * TN * DA];   // normalized t projections [B*T,60]
__device__ float g_Mt[EDIM * EDIM];                // Mt[k][e] = (R_w @ Bc_w)[e][k]
__device__ float g_bias2[EDIM];                    // R_w @ Bc_b + R_b
__device__ float g_S[(size_t)BN * TN * EDIM];      // attn @ u   [B*T,128]

// ---------------------------------------------------------------------------
// packed fp32x2 helpers
// ---------------------------------------------------------------------------
__device__ __forceinline__ ull ffma2(ull a, ull b, ull c) {
    ull d; asm("fma.rn.f32x2 %0,%1,%2,%3;" : "=l"(d) : "l"(a), "l"(b), "l"(c));
    return d;
}
__device__ __forceinline__ ull dup2(float x) {
    ull r; asm("mov.b64 %0,{%1,%1};" : "=l"(r) : "f"(x)); return r;
}
__device__ __forceinline__ float2 upk(ull v) {
    float a, b; asm("mov.b64 {%0,%1},%2;" : "=f"(a), "=f"(b) : "l"(v));
    return make_float2(a, b);
}

// ---------------------------------------------------------------------------
// Kernel 0: fuse M = R_w @ Bc_w (stored transposed) and bias2 = R_w@Bc_b + R_b
// ---------------------------------------------------------------------------
__global__ void fuse_kernel(const float* __restrict__ Rw, const float* __restrict__ Bw,
                            const float* __restrict__ Bb, const float* __restrict__ Rb)
{
    int e = blockIdx.x;
    int k = threadIdx.x;
    __shared__ float sR[EDIM];
    __shared__ float sP[EDIM];
    sR[k] = Rw[e * EDIM + k];
    __syncthreads();
    float acc = 0.f;
#pragma unroll 8
    for (int j = 0; j < EDIM; j++)
        acc = fmaf(sR[j], Bw[j * EDIM + k], acc);
    g_Mt[k * EDIM + e] = acc;     // transposed store
    sP[k] = sR[k] * Bb[k];
    __syncthreads();
    if (k == 0) {
        float s = 0.f;
        for (int j = 0; j < EDIM; j++) s += sP[j];
        g_bias2[e] = s + Rb[e];
    }
}

// ---------------------------------------------------------------------------
// Kernel 1/2: project 64 rows/CTA through W[60,128]+bias, eps-clamped L2 norm.
// GEMM tiling: k split in 2 halves of 64; W staged transposed; thread = 2r x 8d.
// ---------------------------------------------------------------------------
template <bool GATHER>
__global__ __launch_bounds__(256)
void proj_kernel(const float* __restrict__ table,
                 const float* __restrict__ W,
                 const float* __restrict__ bias,
                 const int* __restrict__ idx)
{
    __shared__ __align__(16) float sWt[64][68];          // 17.4 KB (k-half x 64d)
    __shared__ __align__(16) char  arena[64 * 68 * 4];   // 17.4 KB: sX then sOut
    float (*sX)[68]   = (float(*)[68])arena;
    float (*sOut)[68] = (float(*)[68])arena;

    int tid = threadIdx.x;
    int rg = tid >> 3, dg = tid & 7;
    int r0 = 2 * rg, r1 = r0 + 1;
    long base = (long)blockIdx.x * 64;

    ull aA0 = 0, aA1 = 0, aB0 = 0, aB1 = 0;   // row r0: d-chunks A=[4dg,+4), B=[32+4dg,+4)
    ull bA0 = 0, bA1 = 0, bB0 = 0, bB1 = 0;   // row r1

#pragma unroll
    for (int h = 0; h < 2; h++) {
        __syncthreads();
        // stage W half transposed: sWt[kk][d] = W[d][64h+kk]
        for (int i = tid; i < DA * 64; i += 256) {
            int d = i >> 6, kk = i & 63;
            sWt[kk][d] = W[d * EDIM + 64 * h + kk];
        }
        for (int i = tid; i < 64 * 4; i += 256)
            sWt[i >> 2][60 + (i & 3)] = 0.f;
        // stage x half: 64 rows x 64 floats
        for (int i = tid; i < 64 * 16; i += 256) {
            int r = i >> 4, q = i & 15;
            long gr = base + r;
            long rv = GATHER ? (long)idx[gr] : (gr < VSIZE ? gr : (long)(VSIZE - 1));
            ((float4*)&sX[r][0])[q] =
                ((const float4*)(table + rv * EDIM + 64 * h))[q];
        }
        __syncthreads();

#pragma unroll 8
        for (int k = 0; k < 64; k++) {
            ulonglong2 wA = *(const ulonglong2*)&sWt[k][4 * dg];
            ulonglong2 wB = *(const ulonglong2*)&sWt[k][32 + 4 * dg];
            ull x0 = dup2(sX[r0][k]);
            ull x1 = dup2(sX[r1][k]);
            aA0 = ffma2(wA.x, x0, aA0); aA1 = ffma2(wA.y, x0, aA1);
            aB0 = ffma2(wB.x, x0, aB0); aB1 = ffma2(wB.y, x0, aB1);
            bA0 = ffma2(wA.x, x1, bA0); bA1 = ffma2(wA.y, x1, bA1);
            bB0 = ffma2(wB.x, x1, bB0); bB1 = ffma2(wB.y, x1, bB1);
        }
    }
    __syncthreads();   // sX dead -> arena becomes sOut

    {
        // bias from global (small, L2-hot); d>=60 lanes add garbage we never use
        float4 bA = *(const float4*)(bias + 4 * dg);
        float4 bB;
        if (32 + 4 * dg < DA) bB = *(const float4*)(bias + 32 + 4 * dg);
        else                  bB = make_float4(0.f, 0.f, 0.f, 0.f);
        float2 p, q;
        p = upk(aA0); q = upk(aA1);
        *(float4*)&sOut[r0][4 * dg]      = make_float4(p.x + bA.x, p.y + bA.y, q.x + bA.z, q.y + bA.w);
        p = upk(aB0); q = upk(aB1);
        *(float4*)&sOut[r0][32 + 4 * dg] = make_float4(p.x + bB.x, p.y + bB.y, q.x + bB.z, q.y + bB.w);
        p = upk(bA0); q = upk(bA1);
        *(float4*)&sOut[r1][4 * dg]      = make_float4(p.x + bA.x, p.y + bA.y, q.x + bA.z, q.y + bA.w);
        p = upk(bB0); q = upk(bB1);
        *(float4*)&sOut[r1][32 + 4 * dg] = make_float4(p.x + bB.x, p.y + bB.y, q.x + bB.z, q.y + bB.w);
    }
    __syncthreads();

    // normalize + store: warp w handles rows 8w..8w+7
    int w = tid >> 5, l = tid & 31;
    float* outp = GATHER ? g_tprojn : g_cprojn;
#pragma unroll
    for (int rr = 0; rr < 8; rr++) {
        int r = 8 * w + rr;
        long gr = base + r;
        float v0 = sOut[r][l];
        float v1 = (l < DA - 32) ? sOut[r][l + 32] : 0.f;
        float ss = v0 * v0 + v1 * v1;
#pragma unroll
        for (int o = 16; o >= 1; o >>= 1)
            ss += __shfl_xor_sync(0xffffffffu, ss, o);
        float inv = 1.0f / fmaxf(sqrtf(ss), EPSV);
        if (!GATHER && gr >= VSIZE) continue;
        float* op = outp + gr * DA;
        op[l] = v0 * inv;
        if (l < DA - 32) op[l + 32] = v1 * inv;
    }
}

// ---------------------------------------------------------------------------
// Kernel 3: main. One CTA per batch row. P1 scores + P2 softmax + P3 attn@u -> g_S
// ---------------------------------------------------------------------------
__global__ __launch_bounds__(256)
void main_kernel(const float* __restrict__ cvec,
                 const int* __restrict__ citems,
                 const int* __restrict__ maskp,
                 float* __restrict__ outS)
{
    __shared__ int   s_cit[CN];
    __shared__ int   s_mask[CN];
    __shared__ __align__(16) float s_tp[TN][64];
    __shared__ __align__(16) float s_aT[CN][8];         // attn [c][t]
    __shared__ __align__(16) char  arena[8 * 8 * 128 * 4]; // s_cp (27.2K) / s_part (32K)
    float (*s_cp)[68] = (float(*)[68])arena;
    float* s_part = (float*)arena;                      // [p][t][128]

    int b = blockIdx.x;
    int tid = threadIdx.x;
    int w = tid >> 5, l = tid & 31;

    if (tid < CN) {
        s_cit[tid]  = citems[b * CN + tid];
        s_mask[tid] = maskp[b * CN + tid];
    }
    for (int i = tid; i < TN * DA; i += 256) {
        int t = i / DA, d = i - t * DA;
        s_tp[t][d] = g_tprojn[(size_t)b * (TN * DA) + i];
    }

    // ---- Phase 1: scores; warp w = t, lanes own c-columns ----
    float sc[8];
#pragma unroll
    for (int i = 0; i < 8; i++) sc[i] = -1e30f;

    for (int ch = 0; ch < 2; ch++) {
        __syncthreads();
        int base = ch * CCH;
        for (int r = w; r < CCH; r += 8) {
            int tok = s_cit[base + r];
            if (l < 30) {
                float2 v = ((const float2*)(g_cprojn + (size_t)tok * DA))[l];
                *(float2*)&s_cp[r][2 * l] = v;
            }
        }
        __syncthreads();

        ull a0 = 0, a1 = 0, a2 = 0, a3 = 0;
#pragma unroll
        for (int d4 = 0; d4 < 15; d4++) {
            ulonglong2 tp = *(const ulonglong2*)&s_tp[w][4 * d4];
            ulonglong2 c0 = *(const ulonglong2*)&s_cp[l][4 * d4];
            a0 = ffma2(c0.x, tp.x, a0); a0 = ffma2(c0.y, tp.y, a0);
            ulonglong2 c1 = *(const ulonglong2*)&s_cp[l + 32][4 * d4];
            a1 = ffma2(c1.x, tp.x, a1); a1 = ffma2(c1.y, tp.y, a1);
            ulonglong2 c2 = *(const ulonglong2*)&s_cp[l + 64][4 * d4];
            a2 = ffma2(c2.x, tp.x, a2); a2 = ffma2(c2.y, tp.y, a2);
            if (l < 4) {
                ulonglong2 c3 = *(const ulonglong2*)&s_cp[l + 96][4 * d4];
                a3 = ffma2(c3.x, tp.x, a3); a3 = ffma2(c3.y, tp.y, a3);
            }
        }
        {
            float2 f;
            f = upk(a0); sc[ch*4+0] = s_mask[base + l]      ? -1e30f : (f.x + f.y);
            f = upk(a1); sc[ch*4+1] = s_mask[base + l + 32] ? -1e30f : (f.x + f.y);
            f = upk(a2); sc[ch*4+2] = s_mask[base + l + 64] ? -1e30f : (f.x + f.y);
            if (l < 4) {
                f = upk(a3); sc[ch*4+3] = s_mask[base + l + 96] ? -1e30f : (f.x + f.y);
            }
        }
    }

    // ---- Phase 2: softmax over c for t=w ----
    {
        float m = sc[0];
#pragma unroll
        for (int i = 1; i < 8; i++) m = fmaxf(m, sc[i]);
#pragma unroll
        for (int o = 16; o >= 1; o >>= 1)
            m = fmaxf(m, __shfl_xor_sync(0xffffffffu, m, o));
        float sum = 0.f;
#pragma unroll
        for (int i = 0; i < 8; i++) { sc[i] = __expf(sc[i] - m); sum += sc[i]; }
#pragma unroll
        for (int o = 16; o >= 1; o >>= 1)
            sum += __shfl_xor_sync(0xffffffffu, sum, o);
        float inv = 1.0f / sum;
#pragma unroll
        for (int i = 0; i < 8; i++) {
            int cl = l + 32 * (i & 3);
            if (cl < CCH) s_aT[(i >> 2) * CCH + cl][w] = sc[i] * inv;
        }
    }
    __syncthreads();   // also fences last s_cp reads before s_part writes

    // ---- Phase 3: partial s over warp's 25-c chunk; lane owns e=4l..4l+3 ----
    {
        ull acc[16];
#pragma unroll
        for (int i = 0; i < 16; i++) acc[i] = 0;
        int cbeg = 25 * w;
#pragma unroll 5
        for (int c = cbeg; c < cbeg + 25; c++) {
            int tok = s_cit[c];
            ulonglong2 u = *(const ulonglong2*)(cvec + (size_t)tok * EDIM + 4 * l);
            const ulonglong2* ap = (const ulonglong2*)&s_aT[c][0];
            ulonglong2 A = ap[0], B = ap[1];
            float2 f0 = upk(A.x), f1 = upk(A.y), f2 = upk(B.x), f3 = upk(B.y);
            ull d0 = dup2(f0.x), d1 = dup2(f0.y), d2 = dup2(f1.x), d3 = dup2(f1.y);
            ull d4 = dup2(f2.x), d5 = dup2(f2.y), d6 = dup2(f3.x), d7 = dup2(f3.y);
            acc[0]  = ffma2(u.x, d0, acc[0]);  acc[1]  = ffma2(u.y, d0, acc[1]);
            acc[2]  = ffma2(u.x, d1, acc[2]);  acc[3]  = ffma2(u.y, d1, acc[3]);
            acc[4]  = ffma2(u.x, d2, acc[4]);  acc[5]  = ffma2(u.y, d2, acc[5]);
            acc[6]  = ffma2(u.x, d3, acc[6]);  acc[7]  = ffma2(u.y, d3, acc[7]);
            acc[8]  = ffma2(u.x, d4, acc[8]);  acc[9]  = ffma2(u.y, d4, acc[9]);
            acc[10] = ffma2(u.x, d5, acc[10]); acc[11] = ffma2(u.y, d5, acc[11]);
            acc[12] = ffma2(u.x, d6, acc[12]); acc[13] = ffma2(u.y, d6, acc[13]);
            acc[14] = ffma2(u.x, d7, acc[14]); acc[15] = ffma2(u.y, d7, acc[15]);
        }
#pragma unroll
        for (int t = 0; t < TN; t++) {
            ulonglong2 v; v.x = acc[2 * t]; v.y = acc[2 * t + 1];
            *(ulonglong2*)&s_part[(w * TN + t) * EDIM + 4 * l] = v;
        }
    }
    __syncthreads();

    // ---- reduce 8 partials, write S ----
    {
        int t = tid >> 5, e4 = tid & 31;
        float4 s = make_float4(0.f, 0.f, 0.f, 0.f);
#pragma unroll
        for (int p = 0; p < 8; p++) {
            float4 v = *(const float4*)&s_part[(p * TN + t) * EDIM + 4 * e4];
            s.x += v.x; s.y += v.y; s.z += v.z; s.w += v.w;
        }
        *(float4*)(outS + ((size_t)b * TN + t) * EDIM + 4 * e4) = s;
    }
}

// ---------------------------------------------------------------------------
// Kernel 4: Z = S @ Mt + bias2  ([32768,128] x [128,128]), 64 rows per CTA.
// Thread micro-tile: 4 rows x 8 cols, bias folded into accumulator init.
// ---------------------------------------------------------------------------
__global__ __launch_bounds__(256)
void zgemm_kernel(const float* __restrict__ S, float* __restrict__ outp)
{
    __shared__ __align__(16) float sS[64][128];   // 32 KB

    int tid = threadIdx.x;
    int rg = tid >> 4;          // 0..15 -> rows 4rg..4rg+3
    int eg = tid & 15;          // 0..15 -> cols 8eg..8eg+7
    long row0 = (long)blockIdx.x * 64;

    for (int i = tid; i < 64 * 32; i += 256) {
        int r = i >> 5, q = i & 31;
        ((float4*)&sS[r][0])[q] = ((const float4*)(S + (row0 + r) * EDIM))[q];
    }

    // init accumulators with bias
    ull acc[4][4];
    {
        const ulonglong2* bp = (const ulonglong2*)(g_bias2 + 8 * eg);
        ulonglong2 b0 = bp[0], b1 = bp[1];
#pragma unroll
        for (int j = 0; j < 4; j++) {
            acc[j][0] = b0.x; acc[j][1] = b0.y;
            acc[j][2] = b1.x; acc[j][3] = b1.y;
        }
    }
    __syncthreads();

#pragma unroll 4
    for (int k = 0; k < EDIM; k++) {
        const ulonglong2* mp = (const ulonglong2*)(g_Mt + k * EDIM + 8 * eg);
        ulonglong2 m0 = mp[0], m1 = mp[1];
        ull x0 = dup2(sS[4 * rg + 0][k]);
        ull x1 = dup2(sS[4 * rg + 1][k]);
        ull x2 = dup2(sS[4 * rg + 2][k]);
        ull x3 = dup2(sS[4 * rg + 3][k]);
        acc[0][0] = ffma2(m0.x, x0, acc[0][0]); acc[0][1] = ffma2(m0.y, x0, acc[0][1]);
        acc[0][2] = ffma2(m1.x, x0, acc[0][2]); acc[0][3] = ffma2(m1.y, x0, acc[0][3]);
        acc[1][0] = ffma2(m0.x, x1, acc[1][0]); acc[1][1] = ffma2(m0.y, x1, acc[1][1]);
        acc[1][2] = ffma2(m1.x, x1, acc[1][2]); acc[1][3] = ffma2(m1.y, x1, acc[1][3]);
        acc[2][0] = ffma2(m0.x, x2, acc[2][0]); acc[2][1] = ffma2(m0.y, x2, acc[2][1]);
        acc[2][2] = ffma2(m1.x, x2, acc[2][2]); acc[2][3] = ffma2(m1.y, x2, acc[2][3]);
        acc[3][0] = ffma2(m0.x, x3, acc[3][0]); acc[3][1] = ffma2(m0.y, x3, acc[3][1]);
        acc[3][2] = ffma2(m1.x, x3, acc[3][2]); acc[3][3] = ffma2(m1.y, x3, acc[3][3]);
    }

#pragma unroll
    for (int j = 0; j < 4; j++) {
        float* op = outp + (row0 + 4 * rg + j) * EDIM + 8 * eg;
        float2 f0 = upk(acc[j][0]), f1 = upk(acc[j][1]);
        float2 f2 = upk(acc[j][2]), f3 = upk(acc[j][3]);
        *(float4*)(op)     = make_float4(f0.x, f0.y, f1.x, f1.y);
        *(float4*)(op + 4) = make_float4(f2.x, f2.y, f3.x, f3.y);
    }
}

// ---------------------------------------------------------------------------
extern "C" void kernel_launch(void* const* d_in, const int* in_sizes, int n_in,
                              void* d_out, int out_size)
{
    const float* tvec  = (const float*)d_in[0];
    const float* cvec  = (const float*)d_in[1];
    const float* Ac_w  = (const float*)d_in[2];
    const float* Ac_b  = (const float*)d_in[3];
    const float* At_w  = (const float*)d_in[4];
    const float* At_b  = (const float*)d_in[5];
    const float* Bc_w  = (const float*)d_in[6];
    const float* Bc_b  = (const float*)d_in[7];
    const float* R_w   = (const float*)d_in[8];
    const float* R_b   = (const float*)d_in[9];
    const int*   titems = (const int*)d_in[10];
    const int*   citems = (const int*)d_in[11];
    const int*   maskp  = (const int*)d_in[12];

    float* S;
    cudaGetSymbolAddress((void**)&S, g_S);

    fuse_kernel<<<EDIM, EDIM>>>(R_w, Bc_w, Bc_b, R_b);
    proj_kernel<false><<<(VSIZE + 63) / 64, 256>>>(cvec, Ac_w, Ac_b, nullptr);
    proj_kernel<true><<<(BN * TN) / 64, 256>>>(tvec, At_w, At_b, titems);
    main_kernel<<<BN, 256>>>(cvec, citems, maskp, S);
    zgemm_kernel<<<(BN * TN) / 64, 256>>>(S, (float*)d_out);
}

// round 7
// speedup vs baseline: 1.6184x; 1.0402x over previous
#include <cuda_runtime.h>

#define VSIZE 100000
#define EDIM  128
#define DA    60
#define BN    4096
#define TN    8
#define CN    200
#define EPSV  1e-6f
#define CCH   100

typedef unsigned long long ull;

// Scratch (device globals: no allocation allowed)
__device__ float g_cprojn[(size_t)VSIZE * DA];     // normalized c projections [V,60]
__device__ float g_tprojn[(size_t)BN * TN * DA];   // normalized t projections [B*T,60]
__device__ float g_Mt[EDIM * EDIM];                // Mt[k][e] = (R_w @ Bc_w)[e][k]
__device__ float g_bias2[EDIM];                    // R_w @ Bc_b + R_b
__device__ float g_S[(size_t)BN * TN * EDIM];      // attn @ u   [B*T,128]

// ---------------------------------------------------------------------------
// packed fp32x2 helpers
// ---------------------------------------------------------------------------
__device__ __forceinline__ ull ffma2(ull a, ull b, ull c) {
    ull d; asm("fma.rn.f32x2 %0,%1,%2,%3;" : "=l"(d) : "l"(a), "l"(b), "l"(c));
    return d;
}
__device__ __forceinline__ ull dup2(float x) {
    ull r; asm("mov.b64 %0,{%1,%1};" : "=l"(r) : "f"(x)); return r;
}
__device__ __forceinline__ float2 upk(ull v) {
    float a, b; asm("mov.b64 {%0,%1},%2;" : "=f"(a), "=f"(b) : "l"(v));
    return make_float2(a, b);
}

// ---------------------------------------------------------------------------
// Kernel 0: fuse M = R_w @ Bc_w (stored transposed) and bias2 = R_w@Bc_b + R_b
// ---------------------------------------------------------------------------
__global__ void fuse_kernel(const float* __restrict__ Rw, const float* __restrict__ Bw,
                            const float* __restrict__ Bb, const float* __restrict__ Rb)
{
    int e = blockIdx.x;
    int k = threadIdx.x;
    __shared__ float sR[EDIM];
    __shared__ float sP[EDIM];
    sR[k] = Rw[e * EDIM + k];
    __syncthreads();
    float acc = 0.f;
#pragma unroll 8
    for (int j = 0; j < EDIM; j++)
        acc = fmaf(sR[j], Bw[j * EDIM + k], acc);
    g_Mt[k * EDIM + e] = acc;     // transposed store
    sP[k] = sR[k] * Bb[k];
    __syncthreads();
    if (k == 0) {
        float s = 0.f;
        for (int j = 0; j < EDIM; j++) s += sP[j];
        g_bias2[e] = s + Rb[e];
    }
}

// ---------------------------------------------------------------------------
// Kernel 1/2: project 64 rows/CTA through W[60,128]+bias, eps-clamped L2 norm.
// GEMM tiling: k split in 2 halves of 64; W staged transposed; thread = 2r x 8d.
// (R4 version — 34.8 KB static smem, known-good.)
// ---------------------------------------------------------------------------
template <bool GATHER>
__global__ __launch_bounds__(256)
void proj_kernel(const float* __restrict__ table,
                 const float* __restrict__ W,
                 const float* __restrict__ bias,
                 const int* __restrict__ idx)
{
    __shared__ __align__(16) float sWt[64][68];          // 17.4 KB (k-half x 64d)
    __shared__ __align__(16) char  arena[64 * 68 * 4];   // 17.4 KB: sX then sOut
    float (*sX)[68]   = (float(*)[68])arena;
    float (*sOut)[68] = (float(*)[68])arena;

    int tid = threadIdx.x;
    int rg = tid >> 3, dg = tid & 7;
    int r0 = 2 * rg, r1 = r0 + 1;
    long base = (long)blockIdx.x * 64;

    ull aA0 = 0, aA1 = 0, aB0 = 0, aB1 = 0;   // row r0
    ull bA0 = 0, bA1 = 0, bB0 = 0, bB1 = 0;   // row r1

#pragma unroll
    for (int h = 0; h < 2; h++) {
        __syncthreads();
        for (int i = tid; i < DA * 64; i += 256) {
            int d = i >> 6, kk = i & 63;
            sWt[kk][d] = W[d * EDIM + 64 * h + kk];
        }
        for (int i = tid; i < 64 * 4; i += 256)
            sWt[i >> 2][60 + (i & 3)] = 0.f;
        for (int i = tid; i < 64 * 16; i += 256) {
            int r = i >> 4, q = i & 15;
            long gr = base + r;
            long rv = GATHER ? (long)idx[gr] : (gr < VSIZE ? gr : (long)(VSIZE - 1));
            ((float4*)&sX[r][0])[q] =
                ((const float4*)(table + rv * EDIM + 64 * h))[q];
        }
        __syncthreads();

#pragma unroll 8
        for (int k = 0; k < 64; k++) {
            ulonglong2 wA = *(const ulonglong2*)&sWt[k][4 * dg];
            ulonglong2 wB = *(const ulonglong2*)&sWt[k][32 + 4 * dg];
            ull x0 = dup2(sX[r0][k]);
            ull x1 = dup2(sX[r1][k]);
            aA0 = ffma2(wA.x, x0, aA0); aA1 = ffma2(wA.y, x0, aA1);
            aB0 = ffma2(wB.x, x0, aB0); aB1 = ffma2(wB.y, x0, aB1);
            bA0 = ffma2(wA.x, x1, bA0); bA1 = ffma2(wA.y, x1, bA1);
            bB0 = ffma2(wB.x, x1, bB0); bB1 = ffma2(wB.y, x1, bB1);
        }
    }
    __syncthreads();   // sX dead -> arena becomes sOut

    {
        float4 bA = *(const float4*)(bias + 4 * dg);
        float4 bB;
        if (32 + 4 * dg < DA) bB = *(const float4*)(bias + 32 + 4 * dg);
        else                  bB = make_float4(0.f, 0.f, 0.f, 0.f);
        float2 p, q;
        p = upk(aA0); q = upk(aA1);
        *(float4*)&sOut[r0][4 * dg]      = make_float4(p.x + bA.x, p.y + bA.y, q.x + bA.z, q.y + bA.w);
        p = upk(aB0); q = upk(aB1);
        *(float4*)&sOut[r0][32 + 4 * dg] = make_float4(p.x + bB.x, p.y + bB.y, q.x + bB.z, q.y + bB.w);
        p = upk(bA0); q = upk(bA1);
        *(float4*)&sOut[r1][4 * dg]      = make_float4(p.x + bA.x, p.y + bA.y, q.x + bA.z, q.y + bA.w);
        p = upk(bB0); q = upk(bB1);
        *(float4*)&sOut[r1][32 + 4 * dg] = make_float4(p.x + bB.x, p.y + bB.y, q.x + bB.z, q.y + bB.w);
    }
    __syncthreads();

    // normalize + store: warp w handles rows 8w..8w+7
    int w = tid >> 5, l = tid & 31;
    float* outp = GATHER ? g_tprojn : g_cprojn;
#pragma unroll
    for (int rr = 0; rr < 8; rr++) {
        int r = 8 * w + rr;
        long gr = base + r;
        float v0 = sOut[r][l];
        float v1 = (l < DA - 32) ? sOut[r][l + 32] : 0.f;
        float ss = v0 * v0 + v1 * v1;
#pragma unroll
        for (int o = 16; o >= 1; o >>= 1)
            ss += __shfl_xor_sync(0xffffffffu, ss, o);
        float inv = 1.0f / fmaxf(sqrtf(ss), EPSV);
        if (!GATHER && gr >= VSIZE) continue;
        float* op = outp + gr * DA;
        op[l] = v0 * inv;
        if (l < DA - 32) op[l + 32] = v1 * inv;
    }
}

// ---------------------------------------------------------------------------
// Kernel 3: main. One CTA per batch row. P1 scores + P2 softmax + P3 attn@u -> g_S
// launch_bounds(256,4): cap regs at 64 so 4 CTAs/SM (was 3 at 66 regs).
// ---------------------------------------------------------------------------
__global__ __launch_bounds__(256, 4)
void main_kernel(const float* __restrict__ cvec,
                 const int* __restrict__ citems,
                 const int* __restrict__ maskp,
                 float* __restrict__ outS)
{
    __shared__ int   s_cit[CN];
    __shared__ int   s_mask[CN];
    __shared__ __align__(16) float s_tp[TN][64];
    __shared__ __align__(16) float s_aT[CN][8];            // attn [c][t]
    __shared__ __align__(16) char  arena[8 * 8 * 128 * 4]; // s_cp (27.2K) / s_part (32K)
    float (*s_cp)[68] = (float(*)[68])arena;
    float* s_part = (float*)arena;                         // [p][t][128]

    int b = blockIdx.x;
    int tid = threadIdx.x;
    int w = tid >> 5, l = tid & 31;

    if (tid < CN) {
        s_cit[tid]  = citems[b * CN + tid];
        s_mask[tid] = maskp[b * CN + tid];
    }
    for (int i = tid; i < TN * DA; i += 256) {
        int t = i / DA, d = i - t * DA;
        s_tp[t][d] = g_tprojn[(size_t)b * (TN * DA) + i];
    }

    // ---- Phase 1: scores; warp w = t, lanes own c-columns ----
    float sc[8];
#pragma unroll
    for (int i = 0; i < 8; i++) sc[i] = -1e30f;

    for (int ch = 0; ch < 2; ch++) {
        __syncthreads();
        int base = ch * CCH;
        for (int r = w; r < CCH; r += 8) {
            int tok = s_cit[base + r];
            if (l < 30) {
                float2 v = ((const float2*)(g_cprojn + (size_t)tok * DA))[l];
                *(float2*)&s_cp[r][2 * l] = v;
            }
        }
        __syncthreads();

        ull a0 = 0, a1 = 0, a2 = 0, a3 = 0;
#pragma unroll
        for (int d4 = 0; d4 < 15; d4++) {
            ulonglong2 tp = *(const ulonglong2*)&s_tp[w][4 * d4];
            ulonglong2 c0 = *(const ulonglong2*)&s_cp[l][4 * d4];
            a0 = ffma2(c0.x, tp.x, a0); a0 = ffma2(c0.y, tp.y, a0);
            ulonglong2 c1 = *(const ulonglong2*)&s_cp[l + 32][4 * d4];
            a1 = ffma2(c1.x, tp.x, a1); a1 = ffma2(c1.y, tp.y, a1);
            ulonglong2 c2 = *(const ulonglong2*)&s_cp[l + 64][4 * d4];
            a2 = ffma2(c2.x, tp.x, a2); a2 = ffma2(c2.y, tp.y, a2);
            if (l < 4) {
                ulonglong2 c3 = *(const ulonglong2*)&s_cp[l + 96][4 * d4];
                a3 = ffma2(c3.x, tp.x, a3); a3 = ffma2(c3.y, tp.y, a3);
            }
        }
        {
            float2 f;
            f = upk(a0); sc[ch*4+0] = s_mask[base + l]      ? -1e30f : (f.x + f.y);
            f = upk(a1); sc[ch*4+1] = s_mask[base + l + 32] ? -1e30f : (f.x + f.y);
            f = upk(a2); sc[ch*4+2] = s_mask[base + l + 64] ? -1e30f : (f.x + f.y);
            if (l < 4) {
                f = upk(a3); sc[ch*4+3] = s_mask[base + l + 96] ? -1e30f : (f.x + f.y);
            }
        }
    }

    // ---- Phase 2: softmax over c for t=w ----
    {
        float m = sc[0];
#pragma unroll
        for (int i = 1; i < 8; i++) m = fmaxf(m, sc[i]);
#pragma unroll
        for (int o = 16; o >= 1; o >>= 1)
            m = fmaxf(m, __shfl_xor_sync(0xffffffffu, m, o));
        float sum = 0.f;
#pragma unroll
        for (int i = 0; i < 8; i++) { sc[i] = __expf(sc[i] - m); sum += sc[i]; }
#pragma unroll
        for (int o = 16; o >= 1; o >>= 1)
            sum += __shfl_xor_sync(0xffffffffu, sum, o);
        float inv = 1.0f / sum;
#pragma unroll
        for (int i = 0; i < 8; i++) {
            int cl = l + 32 * (i & 3);
            if (cl < CCH) s_aT[(i >> 2) * CCH + cl][w] = sc[i] * inv;
        }
    }
    __syncthreads();   // also fences last s_cp reads before s_part writes

    // ---- Phase 3: partial s over warp's 25-c chunk; lane owns e=4l..4l+3 ----
    {
        ull acc[16];
#pragma unroll
        for (int i = 0; i < 16; i++) acc[i] = 0;
        int cbeg = 25 * w;
#pragma unroll 5
        for (int c = cbeg; c < cbeg + 25; c++) {
            int tok = s_cit[c];
            ulonglong2 u = *(const ulonglong2*)(cvec + (size_t)tok * EDIM + 4 * l);
            const ulonglong2* ap = (const ulonglong2*)&s_aT[c][0];
            {
                ulonglong2 A = ap[0];
                float2 f0 = upk(A.x), f1 = upk(A.y);
                ull d0 = dup2(f0.x), d1 = dup2(f0.y), d2 = dup2(f1.x), d3 = dup2(f1.y);
                acc[0] = ffma2(u.x, d0, acc[0]); acc[1] = ffma2(u.y, d0, acc[1]);
                acc[2] = ffma2(u.x, d1, acc[2]); acc[3] = ffma2(u.y, d1, acc[3]);
                acc[4] = ffma2(u.x, d2, acc[4]); acc[5] = ffma2(u.y, d2, acc[5]);
                acc[6] = ffma2(u.x, d3, acc[6]); acc[7] = ffma2(u.y, d3, acc[7]);
            }
            {
                ulonglong2 B = ap[1];
                float2 f2 = upk(B.x), f3 = upk(B.y);
                ull d4 = dup2(f2.x), d5 = dup2(f2.y), d6 = dup2(f3.x), d7 = dup2(f3.y);
                acc[8]  = ffma2(u.x, d4, acc[8]);  acc[9]  = ffma2(u.y, d4, acc[9]);
                acc[10] = ffma2(u.x, d5, acc[10]); acc[11] = ffma2(u.y, d5, acc[11]);
                acc[12] = ffma2(u.x, d6, acc[12]); acc[13] = ffma2(u.y, d6, acc[13]);
                acc[14] = ffma2(u.x, d7, acc[14]); acc[15] = ffma2(u.y, d7, acc[15]);
            }
        }
#pragma unroll
        for (int t = 0; t < TN; t++) {
            ulonglong2 v; v.x = acc[2 * t]; v.y = acc[2 * t + 1];
            *(ulonglong2*)&s_part[(w * TN + t) * EDIM + 4 * l] = v;
        }
    }
    __syncthreads();

    // ---- reduce 8 partials, write S ----
    {
        int t = tid >> 5, e4 = tid & 31;
        float4 s = make_float4(0.f, 0.f, 0.f, 0.f);
#pragma unroll
        for (int p = 0; p < 8; p++) {
            float4 v = *(const float4*)&s_part[(p * TN + t) * EDIM + 4 * e4];
            s.x += v.x; s.y += v.y; s.z += v.z; s.w += v.w;
        }
        *(float4*)(outS + ((size_t)b * TN + t) * EDIM + 4 * e4) = s;
    }
}

// ---------------------------------------------------------------------------
// Kernel 4: Z = S @ Mt + bias2  ([32768,128] x [128,128]), 64 rows per CTA.
// ---------------------------------------------------------------------------
__global__ __launch_bounds__(256)
void zgemm_kernel(const float* __restrict__ S, float* __restrict__ outp)
{
    __shared__ __align__(16) float sS[64][128];   // 32 KB

    int tid = threadIdx.x;
    int rg = tid >> 4;          // rows 4rg..4rg+3
    int eg = tid & 15;          // cols 8eg..8eg+7
    long row0 = (long)blockIdx.x * 64;

    for (int i = tid; i < 64 * 32; i += 256) {
        int r = i >> 5, q = i & 31;
        ((float4*)&sS[r][0])[q] = ((const float4*)(S + (row0 + r) * EDIM))[q];
    }

    ull acc[4][4];
    {
        const ulonglong2* bp = (const ulonglong2*)(g_bias2 + 8 * eg);
        ulonglong2 b0 = bp[0], b1 = bp[1];
#pragma unroll
        for (int j = 0; j < 4; j++) {
            acc[j][0] = b0.x; acc[j][1] = b0.y;
            acc[j][2] = b1.x; acc[j][3] = b1.y;
        }
    }
    __syncthreads();

#pragma unroll 4
    for (int k = 0; k < EDIM; k++) {
        const ulonglong2* mp = (const ulonglong2*)(g_Mt + k * EDIM + 8 * eg);
        ulonglong2 m0 = mp[0], m1 = mp[1];
        ull x0 = dup2(sS[4 * rg + 0][k]);
        ull x1 = dup2(sS[4 * rg + 1][k]);
        ull x2 = dup2(sS[4 * rg + 2][k]);
        ull x3 = dup2(sS[4 * rg + 3][k]);
        acc[0][0] = ffma2(m0.x, x0, acc[0][0]); acc[0][1] = ffma2(m0.y, x0, acc[0][1]);
        acc[0][2] = ffma2(m1.x, x0, acc[0][2]); acc[0][3] = ffma2(m1.y, x0, acc[0][3]);
        acc[1][0] = ffma2(m0.x, x1, acc[1][0]); acc[1][1] = ffma2(m0.y, x1, acc[1][1]);
        acc[1][2] = ffma2(m1.x, x1, acc[1][2]); acc[1][3] = ffma2(m1.y, x1, acc[1][3]);
        acc[2][0] = ffma2(m0.x, x2, acc[2][0]); acc[2][1] = ffma2(m0.y, x2, acc[2][1]);
        acc[2][2] = ffma2(m1.x, x2, acc[2][2]); acc[2][3] = ffma2(m1.y, x2, acc[2][3]);
        acc[3][0] = ffma2(m0.x, x3, acc[3][0]); acc[3][1] = ffma2(m0.y, x3, acc[3][1]);
        acc[3][2] = ffma2(m1.x, x3, acc[3][2]); acc[3][3] = ffma2(m1.y, x3, acc[3][3]);
    }

#pragma unroll
    for (int j = 0; j < 4; j++) {
        float* op = outp + (row0 + 4 * rg + j) * EDIM + 8 * eg;
        float2 f0 = upk(acc[j][0]), f1 = upk(acc[j][1]);
        float2 f2 = upk(acc[j][2]), f3 = upk(acc[j][3]);
        *(float4*)(op)     = make_float4(f0.x, f0.y, f1.x, f1.y);
        *(float4*)(op + 4) = make_float4(f2.x, f2.y, f3.x, f3.y);
    }
}

// ---------------------------------------------------------------------------
extern "C" void kernel_launch(void* const* d_in, const int* in_sizes, int n_in,
                              void* d_out, int out_size)
{
    const float* tvec  = (const float*)d_in[0];
    const float* cvec  = (const float*)d_in[1];
    const float* Ac_w  = (const float*)d_in[2];
    const float* Ac_b  = (const float*)d_in[3];
    const float* At_w  = (const float*)d_in[4];
    const float* At_b  = (const float*)d_in[5];
    const float* Bc_w  = (const float*)d_in[6];
    const float* Bc_b  = (const float*)d_in[7];
    const float* R_w   = (const float*)d_in[8];
    const float* R_b   = (const float*)d_in[9];
    const int*   titems = (const int*)d_in[10];
    const int*   citems = (const int*)d_in[11];
    const int*   maskp  = (const int*)d_in[12];

    float* S;
    cudaGetSymbolAddress((void**)&S, g_S);

    fuse_kernel<<<EDIM, EDIM>>>(R_w, Bc_w, Bc_b, R_b);
    proj_kernel<false><<<(VSIZE + 63) / 64, 256>>>(cvec, Ac_w, Ac_b, nullptr);
    proj_kernel<true><<<(BN * TN) / 64, 256>>>(tvec, At_w, At_b, titems);
    main_kernel<<<BN, 256>>>(cvec, citems, maskp, S);
    zgemm_kernel<<<(BN * TN) / 64, 256>>>(S, (float*)d_out);
}